// round 3
// baseline (speedup 1.0000x reference)
#include <cuda_runtime.h>
#include <cstdint>

#define NG        1024
#define HB        296            // hist blocks (2 per SM)
#define ITERS     30
#define FIXSCALE  1048576.0f     // 2^20 fixed point for S0
#define INVSCALE  (1.0f / 1048576.0f)
#define CNT_SHIFT 44

typedef unsigned long long ull;

// ---------------- device scratch (no allocations allowed) ----------------
// per-block partial histograms, transposed: g_part[g*HB + b]
__device__ ull   g_part[NG * HB];
__device__ float g_alphas[NG];

// ---------------- pass 1: per-block fixed-point histogram ----------------
__device__ __forceinline__ void hist_one(ull* acc, float a, float b, int g) {
    float yr = fmaxf(b, 1e-9f);
    float r  = __fdividef(a, yr);
    float s  = fminf(fmaxf(r, 0.9f), 1.1f);
    ull v = (ull)(s * FIXSCALE) + (1ull << CNT_SHIFT);
    atomicAdd(&acc[g], v);
}

__global__ void __launch_bounds__(256) k_hist(
        const float4* __restrict__ yraw4, const float4* __restrict__ yreal4,
        const int4* __restrict__ gid4, int n4,
        const float* __restrict__ yraw, const float* __restrict__ yreal,
        const int* __restrict__ gid, int n) {
    __shared__ ull acc[NG];
    for (int i = threadIdx.x; i < NG; i += blockDim.x) acc[i] = 0ull;
    __syncthreads();

    int stride = gridDim.x * blockDim.x;
    #pragma unroll 2
    for (int i = blockIdx.x * blockDim.x + threadIdx.x; i < n4; i += stride) {
        float4 a = yraw4[i];
        float4 b = yreal4[i];
        int4   g = gid4[i];
        hist_one(acc, a.x, b.x, g.x);
        hist_one(acc, a.y, b.y, g.y);
        hist_one(acc, a.z, b.z, g.z);
        hist_one(acc, a.w, b.w, g.w);
    }
    // tail (n not multiple of 4)
    int t = blockIdx.x * blockDim.x + threadIdx.x;
    int base = n4 * 4;
    if (t < n - base) hist_one(acc, yraw[base + t], yreal[base + t], gid[base + t]);

    __syncthreads();
    // plain stores of partials (overwritten every replay -> no zeroing kernel)
    for (int i = threadIdx.x; i < NG; i += blockDim.x)
        g_part[i * HB + blockIdx.x] = acc[i];
}

// ------- pass 2: reduce partials, feasibility, (rare) bisect fallback -------
__global__ void __launch_bounds__(256) k_fb(
        const float* __restrict__ yraw, const float* __restrict__ yreal,
        const int* __restrict__ gid, int n) {
    int g = blockIdx.x;
    int tid = threadIdx.x;

    // deterministic tree reduction of HB partials
    __shared__ ull sred[256];
    ull v = 0ull;
    for (int b = tid; b < HB; b += 256) v += g_part[g * HB + b];
    sred[tid] = v;
    __syncthreads();
    for (int d = 128; d > 0; d >>= 1) {
        if (tid < d) sred[tid] += sred[tid + d];
        __syncthreads();
    }

    __shared__ int   s_infeas;
    __shared__ float s_T;
    __shared__ int   s_cnt;
    if (tid == 0) {
        ull a   = sred[0];
        int cnt = (int)(a >> CNT_SHIFT);
        float S0 = (float)(a & ((1ull << CNT_SHIFT) - 1ull)) * INVSCALE;
        float fn = (float)cnt;
        float L = 0.95f * fn, U = 1.05f * fn;
        bool infeas = (cnt > 0) && (S0 < L || S0 > U);
        s_infeas = infeas ? 1 : 0;
        s_T = (S0 < L) ? L : U;
        s_cnt = cnt;
        g_alphas[g] = 0.0f;
    }
    __syncthreads();
    if (!s_infeas) return;   // fast path: done

    // ---- correctness-only fallback: brute-force bisection over full arrays ----
    __shared__ float sf[256];
    // pass A: min/max of r within group g
    float rmn = __int_as_float(0x7f800000);
    float rmx = __int_as_float(0xff800000);
    for (int i = tid; i < n; i += 256) {
        if (gid[i] == g) {
            float yr = fmaxf(yreal[i], 1e-9f);
            float r  = yraw[i] / yr;
            rmn = fminf(rmn, r);
            rmx = fmaxf(rmx, r);
        }
    }
    sf[tid] = rmn; __syncthreads();
    for (int d = 128; d > 0; d >>= 1) { if (tid < d) sf[tid] = fminf(sf[tid], sf[tid + d]); __syncthreads(); }
    rmn = sf[0]; __syncthreads();
    sf[tid] = rmx; __syncthreads();
    for (int d = 128; d > 0; d >>= 1) { if (tid < d) sf[tid] = fmaxf(sf[tid], sf[tid + d]); __syncthreads(); }
    rmx = sf[0]; __syncthreads();

    float lo = 0.9f - rmx - 1.0f;
    float hi = 1.1f - rmn + 1.0f;
    float T = s_T;
    float mid = lo;
    for (int it = 0; it < ITERS; ++it) {
        mid = 0.5f * (lo + hi);
        float p = 0.0f;
        for (int i = tid; i < n; i += 256) {
            if (gid[i] == g) {
                float yr = fmaxf(yreal[i], 1e-9f);
                float r  = yraw[i] / yr;
                p += fminf(fmaxf(r + mid, 0.9f), 1.1f);
            }
        }
        sf[tid] = p; __syncthreads();
        for (int d = 128; d > 0; d >>= 1) { if (tid < d) sf[tid] += sf[tid + d]; __syncthreads(); }
        float S = sf[0]; __syncthreads();
        if (S < T) lo = mid; else hi = mid;
    }
    if (tid == 0) g_alphas[g] = mid;
}

// ---------------- pass 3: output ----------------
__device__ __forceinline__ float out_one(float a, float b, int g) {
    float yr = fmaxf(b, 1e-9f);
    float alpha = __ldg(&g_alphas[g]);
    float v = fmaf(alpha, yr, a);              // == a exactly when alpha == 0
    return fminf(fmaxf(v, 0.9f * yr), 1.1f * yr);
}

__global__ void __launch_bounds__(256) k_out(
        const float4* __restrict__ yraw4, const float4* __restrict__ yreal4,
        const int4* __restrict__ gid4, float4* __restrict__ out4, int n4,
        const float* __restrict__ yraw, const float* __restrict__ yreal,
        const int* __restrict__ gid, float* __restrict__ out, int n) {
    int stride = gridDim.x * blockDim.x;
    #pragma unroll 2
    for (int i = blockIdx.x * blockDim.x + threadIdx.x; i < n4; i += stride) {
        float4 a = yraw4[i];
        float4 b = yreal4[i];
        int4   g = gid4[i];
        float4 o;
        o.x = out_one(a.x, b.x, g.x);
        o.y = out_one(a.y, b.y, g.y);
        o.z = out_one(a.z, b.z, g.z);
        o.w = out_one(a.w, b.w, g.w);
        out4[i] = o;
    }
    int t = blockIdx.x * blockDim.x + threadIdx.x;
    int base = n4 * 4;
    if (t < n - base) out[base + t] = out_one(yraw[base + t], yreal[base + t], gid[base + t]);
}

// ---------------- launch ----------------
extern "C" void kernel_launch(void* const* d_in, const int* in_sizes, int n_in,
                              void* d_out, int out_size) {
    const float* yraw  = (const float*)d_in[0];
    const float* yreal = (const float*)d_in[1];
    const int*   gid   = (const int*)d_in[2];
    float* out = (float*)d_out;
    int n  = in_sizes[0];
    int n4 = n >> 2;

    k_hist<<<HB, 256>>>((const float4*)yraw, (const float4*)yreal, (const int4*)gid, n4,
                        yraw, yreal, gid, n);
    k_fb<<<NG, 256>>>(yraw, yreal, gid, n);
    k_out<<<1184, 256>>>((const float4*)yraw, (const float4*)yreal, (const int4*)gid,
                         (float4*)d_out, n4, yraw, yreal, gid, out, n);
}

// round 4
// speedup vs baseline: 1.1757x; 1.1757x over previous
#include <cuda_runtime.h>
#include <cstdint>

#define NG        1024
#define HB        592            // hist blocks: 4 per SM, one exact wave
#define HT        512            // hist threads per block
#define ITERS     30
#define FIXSCALE  1048576.0f     // 2^20 fixed point for S0
#define INVSCALE  (1.0f / 1048576.0f)
#define CNT_SHIFT 44

typedef unsigned long long ull;

// ---------------- device scratch (no allocations allowed) ----------------
// per-block partial histograms, transposed: g_part[g*HB + b]
__device__ ull   g_part[NG * HB];
__device__ float g_alphas[NG];

// ---------------- pass 1: per-block fixed-point histogram ----------------
__device__ __forceinline__ void hist_one(ull* acc, float a, float b, int g) {
    float yr = fmaxf(b, 1e-9f);
    float r  = __fdividef(a, yr);
    float s  = fminf(fmaxf(r, 0.9f), 1.1f);
    ull v = (ull)(s * FIXSCALE) + (1ull << CNT_SHIFT);
    atomicAdd(&acc[g], v);
}

__global__ void __launch_bounds__(HT, 4) k_hist(
        const float4* __restrict__ yraw4, const float4* __restrict__ yreal4,
        const int4* __restrict__ gid4, int n4,
        const float* __restrict__ yraw, const float* __restrict__ yreal,
        const int* __restrict__ gid, int n) {
    __shared__ ull acc[NG];
    for (int i = threadIdx.x; i < NG; i += HT) acc[i] = 0ull;
    __syncthreads();

    int stride = gridDim.x * HT;
    #pragma unroll 2
    for (int i = blockIdx.x * HT + threadIdx.x; i < n4; i += stride) {
        float4 a = yraw4[i];
        float4 b = yreal4[i];
        int4   g = gid4[i];
        hist_one(acc, a.x, b.x, g.x);
        hist_one(acc, a.y, b.y, g.y);
        hist_one(acc, a.z, b.z, g.z);
        hist_one(acc, a.w, b.w, g.w);
    }
    // tail (n not multiple of 4)
    int t = blockIdx.x * HT + threadIdx.x;
    int base = n4 * 4;
    if (t < n - base) hist_one(acc, yraw[base + t], yreal[base + t], gid[base + t]);

    __syncthreads();
    // plain stores of partials (overwritten every replay -> no zeroing kernel)
    for (int i = threadIdx.x; i < NG; i += HT)
        g_part[i * HB + blockIdx.x] = acc[i];
}

// ------- pass 2: reduce partials, feasibility, (rare) bisect fallback -------
__global__ void __launch_bounds__(256) k_fb(
        const float* __restrict__ yraw, const float* __restrict__ yreal,
        const int* __restrict__ gid, int n) {
    int g = blockIdx.x;
    int tid = threadIdx.x;

    // deterministic tree reduction of HB partials
    __shared__ ull sred[256];
    ull v = 0ull;
    for (int b = tid; b < HB; b += 256) v += g_part[g * HB + b];
    sred[tid] = v;
    __syncthreads();
    for (int d = 128; d > 0; d >>= 1) {
        if (tid < d) sred[tid] += sred[tid + d];
        __syncthreads();
    }

    __shared__ int   s_infeas;
    __shared__ float s_T;
    if (tid == 0) {
        ull a   = sred[0];
        int cnt = (int)(a >> CNT_SHIFT);
        float S0 = (float)(a & ((1ull << CNT_SHIFT) - 1ull)) * INVSCALE;
        float fn = (float)cnt;
        float L = 0.95f * fn, U = 1.05f * fn;
        bool infeas = (cnt > 0) && (S0 < L || S0 > U);
        s_infeas = infeas ? 1 : 0;
        s_T = (S0 < L) ? L : U;
        g_alphas[g] = 0.0f;
    }
    __syncthreads();
    if (!s_infeas) return;   // fast path: done

    // ---- correctness-only fallback: brute-force bisection over full arrays ----
    __shared__ float sf[256];
    float rmn = __int_as_float(0x7f800000);
    float rmx = __int_as_float(0xff800000);
    for (int i = tid; i < n; i += 256) {
        if (gid[i] == g) {
            float yr = fmaxf(yreal[i], 1e-9f);
            float r  = yraw[i] / yr;
            rmn = fminf(rmn, r);
            rmx = fmaxf(rmx, r);
        }
    }
    sf[tid] = rmn; __syncthreads();
    for (int d = 128; d > 0; d >>= 1) { if (tid < d) sf[tid] = fminf(sf[tid], sf[tid + d]); __syncthreads(); }
    rmn = sf[0]; __syncthreads();
    sf[tid] = rmx; __syncthreads();
    for (int d = 128; d > 0; d >>= 1) { if (tid < d) sf[tid] = fmaxf(sf[tid], sf[tid + d]); __syncthreads(); }
    rmx = sf[0]; __syncthreads();

    float lo = 0.9f - rmx - 1.0f;
    float hi = 1.1f - rmn + 1.0f;
    float T = s_T;
    float mid = lo;
    for (int it = 0; it < ITERS; ++it) {
        mid = 0.5f * (lo + hi);
        float p = 0.0f;
        for (int i = tid; i < n; i += 256) {
            if (gid[i] == g) {
                float yr = fmaxf(yreal[i], 1e-9f);
                float r  = yraw[i] / yr;
                p += fminf(fmaxf(r + mid, 0.9f), 1.1f);
            }
        }
        sf[tid] = p; __syncthreads();
        for (int d = 128; d > 0; d >>= 1) { if (tid < d) sf[tid] += sf[tid + d]; __syncthreads(); }
        float S = sf[0]; __syncthreads();
        if (S < T) lo = mid; else hi = mid;
    }
    if (tid == 0) g_alphas[g] = mid;
}

// ---------------- pass 3: output ----------------
__device__ __forceinline__ float out_one(float a, float b, int g) {
    float yr = fmaxf(b, 1e-9f);
    float alpha = __ldg(&g_alphas[g]);
    float v = fmaf(alpha, yr, a);              // == a exactly when alpha == 0
    return fminf(fmaxf(v, 0.9f * yr), 1.1f * yr);
}

__global__ void __launch_bounds__(256) k_out(
        const float4* __restrict__ yraw4, const float4* __restrict__ yreal4,
        const int4* __restrict__ gid4, float4* __restrict__ out4, int n4,
        const float* __restrict__ yraw, const float* __restrict__ yreal,
        const int* __restrict__ gid, float* __restrict__ out, int n) {
    int stride = gridDim.x * blockDim.x;
    #pragma unroll 2
    for (int i = blockIdx.x * blockDim.x + threadIdx.x; i < n4; i += stride) {
        float4 a = yraw4[i];
        float4 b = yreal4[i];
        int4   g = gid4[i];
        float4 o;
        o.x = out_one(a.x, b.x, g.x);
        o.y = out_one(a.y, b.y, g.y);
        o.z = out_one(a.z, b.z, g.z);
        o.w = out_one(a.w, b.w, g.w);
        out4[i] = o;
    }
    int t = blockIdx.x * blockDim.x + threadIdx.x;
    int base = n4 * 4;
    if (t < n - base) out[base + t] = out_one(yraw[base + t], yreal[base + t], gid[base + t]);
}

// ---------------- launch ----------------
extern "C" void kernel_launch(void* const* d_in, const int* in_sizes, int n_in,
                              void* d_out, int out_size) {
    const float* yraw  = (const float*)d_in[0];
    const float* yreal = (const float*)d_in[1];
    const int*   gid   = (const int*)d_in[2];
    float* out = (float*)d_out;
    int n  = in_sizes[0];
    int n4 = n >> 2;

    k_hist<<<HB, HT>>>((const float4*)yraw, (const float4*)yreal, (const int4*)gid, n4,
                       yraw, yreal, gid, n);
    k_fb<<<NG, 256>>>(yraw, yreal, gid, n);
    k_out<<<1184, 256>>>((const float4*)yraw, (const float4*)yreal, (const int4*)gid,
                         (float4*)d_out, n4, yraw, yreal, gid, out, n);
}